// round 1
// baseline (speedup 1.0000x reference)
#include <cuda_runtime.h>

#define N_NODES 50000
#define N_EDGES 800000
#define H 64
#define RES 0.5f
#define INV_1PRES (1.0f / (1.0f + RES))

// ---------------- device scratch (no allocation allowed) ----------------
__device__ float g_s1[N_NODES];
__device__ float g_s2[N_NODES];      // att_b folded in
__device__ float g_rowsum[N_NODES];
__device__ float g_expatt[N_EDGES];

typedef unsigned long long u64;

__device__ __forceinline__ u64 pack2(float lo, float hi) {
    u64 r;
    asm("mov.b64 %0, {%1, %2};" : "=l"(r) : "f"(lo), "f"(hi));
    return r;
}
__device__ __forceinline__ void unpack2(u64 v, float& lo, float& hi) {
    asm("mov.b64 {%0, %1}, %2;" : "=f"(lo), "=f"(hi) : "l"(v));
}
__device__ __forceinline__ u64 ffma2(u64 a, u64 b, u64 c) {
    u64 d;
    asm("fma.rn.f32x2 %0, %1, %2, %3;" : "=l"(d) : "l"(a), "l"(b), "l"(c));
    return d;
}

// ------------------------------------------------------------------------
// Kernel 1: per-node attention scalars s1, s2; also zero rowsum + out block.
//   s1[i] = relu(x_i @ W1 + b1) . att_w[:H]
//   s2[i] = relu(x_i @ W2 + b2) . att_w[H:] + att_b
// ------------------------------------------------------------------------
__global__ __launch_bounds__(128)
void gat_node_kernel(const float* __restrict__ embeds,
                     const float* __restrict__ W1, const float* __restrict__ b1,
                     const float* __restrict__ W2, const float* __restrict__ b2,
                     const float* __restrict__ att_w, const float* __restrict__ att_b,
                     float* __restrict__ out_part) {
    __shared__ float sW1[H * H];
    __shared__ float sW2[H * H];
    __shared__ float sb1[H], sb2[H], saw[2 * H];
    __shared__ float sab;

    int tid = threadIdx.x;
    for (int i = tid; i < H * H; i += blockDim.x) { sW1[i] = W1[i]; sW2[i] = W2[i]; }
    if (tid < H)      { sb1[tid] = b1[tid]; sb2[tid] = b2[tid]; }
    for (int i = tid; i < 2 * H; i += blockDim.x) saw[i] = att_w[i];
    if (tid == 0) sab = att_b[0];
    __syncthreads();

    int node = blockIdx.x * blockDim.x + tid;
    if (node >= N_NODES) return;

    // x (64 floats) in registers
    float x[H];
    const float4* xr = (const float4*)(embeds + (size_t)node * H);
#pragma unroll
    for (int q = 0; q < 16; q++) {
        float4 v = xr[q];
        x[4 * q + 0] = v.x; x[4 * q + 1] = v.y; x[4 * q + 2] = v.z; x[4 * q + 3] = v.w;
    }

    const u64* W1p = (const u64*)sW1;
    const u64* W2p = (const u64*)sW2;
    u64 acc[32];

    // ---- branch 1: t = x @ W1 + b1 ----
#pragma unroll
    for (int p = 0; p < 32; p++) acc[p] = pack2(sb1[2 * p], sb1[2 * p + 1]);
    for (int k = 0; k < H; k++) {
        u64 xp = pack2(x[k], x[k]);
        const u64* wrow = W1p + k * 32;
#pragma unroll
        for (int p = 0; p < 32; p++) acc[p] = ffma2(xp, wrow[p], acc[p]);
    }
    float s1 = 0.f;
#pragma unroll
    for (int p = 0; p < 32; p++) {
        float a, b;
        unpack2(acc[p], a, b);
        s1 += fmaxf(a, 0.f) * saw[2 * p] + fmaxf(b, 0.f) * saw[2 * p + 1];
    }

    // ---- branch 2: t = x @ W2 + b2 ----
#pragma unroll
    for (int p = 0; p < 32; p++) acc[p] = pack2(sb2[2 * p], sb2[2 * p + 1]);
    for (int k = 0; k < H; k++) {
        u64 xp = pack2(x[k], x[k]);
        const u64* wrow = W2p + k * 32;
#pragma unroll
        for (int p = 0; p < 32; p++) acc[p] = ffma2(xp, wrow[p], acc[p]);
    }
    float s2 = 0.f;
#pragma unroll
    for (int p = 0; p < 32; p++) {
        float a, b;
        unpack2(acc[p], a, b);
        s2 += fmaxf(a, 0.f) * saw[H + 2 * p] + fmaxf(b, 0.f) * saw[H + 2 * p + 1];
    }

    g_s1[node] = s1;
    g_s2[node] = s2 + sab;
    g_rowsum[node] = 0.f;

    // zero the SpMM output row (d_out is poisoned)
    float4 z = make_float4(0.f, 0.f, 0.f, 0.f);
    float4* op = (float4*)(out_part + (size_t)node * H);
#pragma unroll
    for (int q = 0; q < 16; q++) op[q] = z;
}

// ------------------------------------------------------------------------
// Kernel 2: per-edge exp(att) + segment-sum of denominators
// ------------------------------------------------------------------------
__global__ __launch_bounds__(256)
void gat_edge_att_kernel(const int* __restrict__ edge_index) {
    int e = blockIdx.x * blockDim.x + threadIdx.x;
    if (e >= N_EDGES) return;
    int r = edge_index[e];
    int c = edge_index[N_EDGES + e];
    float ea = __expf(g_s1[r] + g_s2[c]);
    g_expatt[e] = ea;
    atomicAdd(&g_rowsum[r], ea);
}

// ------------------------------------------------------------------------
// Kernel 3: per-edge value + SpMM scatter (16 threads per edge, float4 red)
// ------------------------------------------------------------------------
__global__ __launch_bounds__(256)
void gat_edge_spmm_kernel(const int* __restrict__ edge_index,
                          const float* __restrict__ adj_values,
                          const float* __restrict__ embeds,
                          float* __restrict__ values,
                          float* __restrict__ out_part) {
    unsigned gid = blockIdx.x * blockDim.x + threadIdx.x;
    unsigned e = gid >> 4;
    if (e >= N_EDGES) return;
    unsigned lane = threadIdx.x & 31u;
    unsigned sub = gid & 15u;

    int r = 0, c = 0;
    float v = 0.f;
    if (sub == 0) {
        r = edge_index[e];
        c = edge_index[N_EDGES + e];
        float ea = g_expatt[e];
        float rs = g_rowsum[r] + 1e-6f;
        v = (ea / rs + RES * adj_values[e]) * INV_1PRES;
        values[e] = v;
    }
    unsigned base = lane & 16u;  // leader lane of this 16-thread group
    v = __shfl_sync(0xffffffffu, v, base);
    r = __shfl_sync(0xffffffffu, r, base);
    c = __shfl_sync(0xffffffffu, c, base);

    float4 ev = *(const float4*)(embeds + (size_t)c * H + sub * 4);
    float* dst = out_part + (size_t)r * H + sub * 4;
    asm volatile("red.global.add.v4.f32 [%0], {%1, %2, %3, %4};"
                 :: "l"(dst), "f"(ev.x * v), "f"(ev.y * v), "f"(ev.z * v), "f"(ev.w * v)
                 : "memory");
}

// ------------------------------------------------------------------------
extern "C" void kernel_launch(void* const* d_in, const int* in_sizes, int n_in,
                              void* d_out, int out_size) {
    const int*   edge_index = (const int*)d_in[0];
    const float* adj_values = (const float*)d_in[1];
    const float* embeds     = (const float*)d_in[2];
    const float* W1         = (const float*)d_in[3];
    const float* b1         = (const float*)d_in[4];
    const float* W2         = (const float*)d_in[5];
    const float* b2         = (const float*)d_in[6];
    const float* att_w      = (const float*)d_in[7];
    const float* att_b      = (const float*)d_in[8];

    float* values   = (float*)d_out;            // [E]
    float* out_part = (float*)d_out + N_EDGES;  // [N, H]

    gat_node_kernel<<<(N_NODES + 127) / 128, 128>>>(
        embeds, W1, b1, W2, b2, att_w, att_b, out_part);

    gat_edge_att_kernel<<<(N_EDGES + 255) / 256, 256>>>(edge_index);

    gat_edge_spmm_kernel<<<(N_EDGES * 16 + 255) / 256, 256>>>(
        edge_index, adj_values, embeds, values, out_part);
}

// round 2
// speedup vs baseline: 1.1615x; 1.1615x over previous
#include <cuda_runtime.h>

#define N_NODES 50000
#define N_EDGES 800000
#define H 64
#define RES 0.5f
#define INV_1PRES (1.0f / (1.0f + RES))

// ---------------- device scratch (no allocation allowed) ----------------
__device__ float g_s1[N_NODES];
__device__ float g_s2[N_NODES];      // att_b folded in
__device__ float g_rowsum[N_NODES];
__device__ float g_expatt[N_EDGES];

typedef unsigned long long u64;

__device__ __forceinline__ u64 pack2(float lo, float hi) {
    u64 r;
    asm("mov.b64 %0, {%1, %2};" : "=l"(r) : "f"(lo), "f"(hi));
    return r;
}
__device__ __forceinline__ void unpack2(u64 v, float& lo, float& hi) {
    asm("mov.b64 {%0, %1}, %2;" : "=f"(lo), "=f"(hi) : "l"(v));
}
__device__ __forceinline__ u64 ffma2(u64 a, u64 b, u64 c) {
    u64 d;
    asm("fma.rn.f32x2 %0, %1, %2, %3;" : "=l"(d) : "l"(a), "l"(b), "l"(c));
    return d;
}

// ------------------------------------------------------------------------
// Kernel 1: tiled dual-GEMM for per-node attention scalars.
//   Block(128) handles a 64-node tile: C1 = X@W1, C2 = X@W2 (64x64 each),
//   then s1 = att_w[:H].relu(C1+b1), s2 = att_w[H:].relu(C2+b2)+att_b.
//   Thread (ng=tid&15, cg=tid>>4): 4 nodes x 8 cols x 2 mats in f32x2 regs.
//   Also zeroes g_rowsum and the output SpMM region.
// ------------------------------------------------------------------------
__global__ __launch_bounds__(128)
void gat_node_kernel(const float* __restrict__ embeds,
                     const float* __restrict__ W1, const float* __restrict__ b1,
                     const float* __restrict__ W2, const float* __restrict__ b2,
                     const float* __restrict__ att_w, const float* __restrict__ att_b,
                     float* __restrict__ out_part) {
    __shared__ float Xs[64 * 64];    // k-major: Xs[k*64 + node_local]
    __shared__ float W1s[64 * 64];   // row-major: W1s[k*64 + j]
    __shared__ float W2s[64 * 64];

    const int tid = threadIdx.x;
    const int tile = blockIdx.x * 64;
    const int ng = tid & 15;   // node group: nodes ng*4 .. ng*4+3
    const int cg = tid >> 4;   // col group:  cols  cg*8 .. cg*8+7

    // ---- load W1, W2 (coalesced float4 copies) ----
    {
        const float4* w1g = (const float4*)W1;
        const float4* w2g = (const float4*)W2;
        float4* w1s = (float4*)W1s;
        float4* w2s = (float4*)W2s;
#pragma unroll
        for (int i = 0; i < 8; i++) {
            int idx = tid + i * 128;
            w1s[idx] = w1g[idx];
            w2s[idx] = w2g[idx];
        }
    }
    // ---- load X tile, transpose to k-major ----
    {
        const float4* xg = (const float4*)embeds;
#pragma unroll
        for (int i = 0; i < 8; i++) {
            int idx = tid + i * 128;          // [0,1024)
            int nl = idx >> 4;                // node local 0..63
            int k4 = idx & 15;                // float4 index within row
            int node = tile + nl;
            if (node > N_NODES - 1) node = N_NODES - 1;
            float4 v = xg[(size_t)node * 16 + k4];
            Xs[(4 * k4 + 0) * 64 + nl] = v.x;
            Xs[(4 * k4 + 1) * 64 + nl] = v.y;
            Xs[(4 * k4 + 2) * 64 + nl] = v.z;
            Xs[(4 * k4 + 3) * 64 + nl] = v.w;
        }
    }
    __syncthreads();

    // ---- main loop: 32 f32x2 accumulators ----
    u64 acc1[4][4], acc2[4][4];
#pragma unroll
    for (int n = 0; n < 4; n++)
#pragma unroll
        for (int j = 0; j < 4; j++) { acc1[n][j] = 0ULL; acc2[n][j] = 0ULL; }

#pragma unroll 4
    for (int k = 0; k < 64; k++) {
        float4 xv = *(const float4*)(Xs + k * 64 + ng * 4);
        u64 xp[4];
        xp[0] = pack2(xv.x, xv.x);
        xp[1] = pack2(xv.y, xv.y);
        xp[2] = pack2(xv.z, xv.z);
        xp[3] = pack2(xv.w, xv.w);
        const float* w1r = W1s + k * 64 + cg * 8;
        const float* w2r = W2s + k * 64 + cg * 8;
        ulonglong2 w1a = *(const ulonglong2*)(w1r);
        ulonglong2 w1b = *(const ulonglong2*)(w1r + 4);
        ulonglong2 w2a = *(const ulonglong2*)(w2r);
        ulonglong2 w2b = *(const ulonglong2*)(w2r + 4);
#pragma unroll
        for (int n = 0; n < 4; n++) {
            acc1[n][0] = ffma2(xp[n], w1a.x, acc1[n][0]);
            acc1[n][1] = ffma2(xp[n], w1a.y, acc1[n][1]);
            acc1[n][2] = ffma2(xp[n], w1b.x, acc1[n][2]);
            acc1[n][3] = ffma2(xp[n], w1b.y, acc1[n][3]);
            acc2[n][0] = ffma2(xp[n], w2a.x, acc2[n][0]);
            acc2[n][1] = ffma2(xp[n], w2a.y, acc2[n][1]);
            acc2[n][2] = ffma2(xp[n], w2b.x, acc2[n][2]);
            acc2[n][3] = ffma2(xp[n], w2b.y, acc2[n][3]);
        }
    }

    // ---- epilogue: bias + relu + att_w dot over this thread's 8 cols ----
    float b1v[8], b2v[8], aw1[8], aw2[8];
    {
        float4 t;
        t = __ldg((const float4*)(b1 + cg * 8));     b1v[0]=t.x;b1v[1]=t.y;b1v[2]=t.z;b1v[3]=t.w;
        t = __ldg((const float4*)(b1 + cg * 8 + 4)); b1v[4]=t.x;b1v[5]=t.y;b1v[6]=t.z;b1v[7]=t.w;
        t = __ldg((const float4*)(b2 + cg * 8));     b2v[0]=t.x;b2v[1]=t.y;b2v[2]=t.z;b2v[3]=t.w;
        t = __ldg((const float4*)(b2 + cg * 8 + 4)); b2v[4]=t.x;b2v[5]=t.y;b2v[6]=t.z;b2v[7]=t.w;
        t = __ldg((const float4*)(att_w + cg * 8));      aw1[0]=t.x;aw1[1]=t.y;aw1[2]=t.z;aw1[3]=t.w;
        t = __ldg((const float4*)(att_w + cg * 8 + 4));  aw1[4]=t.x;aw1[5]=t.y;aw1[6]=t.z;aw1[7]=t.w;
        t = __ldg((const float4*)(att_w + H + cg * 8));     aw2[0]=t.x;aw2[1]=t.y;aw2[2]=t.z;aw2[3]=t.w;
        t = __ldg((const float4*)(att_w + H + cg * 8 + 4)); aw2[4]=t.x;aw2[5]=t.y;aw2[6]=t.z;aw2[7]=t.w;
    }

    float p1[4], p2[4];
#pragma unroll
    for (int n = 0; n < 4; n++) {
        float s1 = 0.f, s2 = 0.f;
#pragma unroll
        for (int j = 0; j < 4; j++) {
            float a, b;
            unpack2(acc1[n][j], a, b);
            s1 += fmaxf(a + b1v[2 * j], 0.f) * aw1[2 * j]
                + fmaxf(b + b1v[2 * j + 1], 0.f) * aw1[2 * j + 1];
            unpack2(acc2[n][j], a, b);
            s2 += fmaxf(a + b2v[2 * j], 0.f) * aw2[2 * j]
                + fmaxf(b + b2v[2 * j + 1], 0.f) * aw2[2 * j + 1];
        }
        p1[n] = s1;
        p2[n] = s2;
    }

    // ---- cross-colgroup reduction via smem (reuse Xs) ----
    __syncthreads();  // everyone done reading Xs
    float* red1 = Xs;          // [64 nodes][8 cg]
    float* red2 = Xs + 512;
#pragma unroll
    for (int n = 0; n < 4; n++) {
        int nl = ng * 4 + n;
        red1[nl * 8 + cg] = p1[n];
        red2[nl * 8 + cg] = p2[n];
    }
    __syncthreads();

    if (tid < 64) {
        int node = tile + tid;
        if (node < N_NODES) {
            float s1 = 0.f, s2 = 0.f;
#pragma unroll
            for (int c = 0; c < 8; c++) { s1 += red1[tid * 8 + c]; s2 += red2[tid * 8 + c]; }
            g_s1[node] = s1;
            g_s2[node] = s2 + __ldg(att_b);
            g_rowsum[node] = 0.f;
        }
    }

    // ---- zero output SpMM region (d_out is poisoned) ----
    {
        float4 z = make_float4(0.f, 0.f, 0.f, 0.f);
        float4* op = (float4*)(out_part + (size_t)tile * H);
        int lim = N_NODES - tile;          // nodes valid in this tile
        if (lim > 64) lim = 64;
        int lim4 = lim * 16;               // float4s valid
#pragma unroll
        for (int i = 0; i < 8; i++) {
            int idx = tid + i * 128;
            if (idx < lim4) op[idx] = z;
        }
    }
}

// ------------------------------------------------------------------------
// Kernel 2: per-edge exp(att) + segment-sum of denominators
// ------------------------------------------------------------------------
__global__ __launch_bounds__(256)
void gat_edge_att_kernel(const int* __restrict__ edge_index) {
    int e = blockIdx.x * blockDim.x + threadIdx.x;
    if (e >= N_EDGES) return;
    int r = edge_index[e];
    int c = edge_index[N_EDGES + e];
    float ea = __expf(g_s1[r] + g_s2[c]);
    g_expatt[e] = ea;
    atomicAdd(&g_rowsum[r], ea);
}

// ------------------------------------------------------------------------
// Kernel 3: per-edge value + SpMM scatter (16 threads per edge, float4 red)
// ------------------------------------------------------------------------
__global__ __launch_bounds__(256)
void gat_edge_spmm_kernel(const int* __restrict__ edge_index,
                          const float* __restrict__ adj_values,
                          const float* __restrict__ embeds,
                          float* __restrict__ values,
                          float* __restrict__ out_part) {
    unsigned gid = blockIdx.x * blockDim.x + threadIdx.x;
    unsigned e = gid >> 4;
    if (e >= N_EDGES) return;
    unsigned lane = threadIdx.x & 31u;
    unsigned sub = gid & 15u;

    int r = 0, c = 0;
    float v = 0.f;
    if (sub == 0) {
        r = edge_index[e];
        c = edge_index[N_EDGES + e];
        float ea = g_expatt[e];
        float rs = g_rowsum[r] + 1e-6f;
        v = (ea / rs + RES * adj_values[e]) * INV_1PRES;
        values[e] = v;
    }
    unsigned base = lane & 16u;  // leader lane of this 16-thread group
    v = __shfl_sync(0xffffffffu, v, base);
    r = __shfl_sync(0xffffffffu, r, base);
    c = __shfl_sync(0xffffffffu, c, base);

    float4 ev = *(const float4*)(embeds + (size_t)c * H + sub * 4);
    float* dst = out_part + (size_t)r * H + sub * 4;
    asm volatile("red.global.add.v4.f32 [%0], {%1, %2, %3, %4};"
                 :: "l"(dst), "f"(ev.x * v), "f"(ev.y * v), "f"(ev.z * v), "f"(ev.w * v)
                 : "memory");
}

// ------------------------------------------------------------------------
extern "C" void kernel_launch(void* const* d_in, const int* in_sizes, int n_in,
                              void* d_out, int out_size) {
    const int*   edge_index = (const int*)d_in[0];
    const float* adj_values = (const float*)d_in[1];
    const float* embeds     = (const float*)d_in[2];
    const float* W1         = (const float*)d_in[3];
    const float* b1         = (const float*)d_in[4];
    const float* W2         = (const float*)d_in[5];
    const float* b2         = (const float*)d_in[6];
    const float* att_w      = (const float*)d_in[7];
    const float* att_b      = (const float*)d_in[8];

    float* values   = (float*)d_out;            // [E]
    float* out_part = (float*)d_out + N_EDGES;  // [N, H]

    gat_node_kernel<<<(N_NODES + 63) / 64, 128>>>(
        embeds, W1, b1, W2, b2, att_w, att_b, out_part);

    gat_edge_att_kernel<<<(N_EDGES + 255) / 256, 256>>>(edge_index);

    gat_edge_spmm_kernel<<<(N_EDGES * 16 + 255) / 256, 256>>>(
        edge_index, adj_values, embeds, values, out_part);
}